// round 16
// baseline (speedup 1.0000x reference)
#include <cuda_runtime.h>
#include <cuda_bf16.h>
#include <cstdint>
#include <math.h>

#define BATCH 4
#define NVIEW 6
#define DMODEL 128
#define QLEN 1024
#define KLEN 640
#define MHEAD 4
#define DH 64
#define MD 256
#define KTOT (NVIEW*KLEN)   // 3840
#define BM (BATCH*MHEAD)    // 16

// ---------------- scratch (device globals; no allocation allowed) -------------
__device__ __nv_bfloat16 g_qh[BM * NVIEW * QLEN * DH];
__device__ __nv_bfloat16 g_kh[BM * KTOT * DH];
__device__ __nv_bfloat16 g_vh[BM * KTOT * DH];
__device__ float g_po[2][BATCH * QLEN * MD];
__device__ float g_pl[2][BM * QLEN];
__device__ float g_maskb[NVIEW * QLEN];
__device__ char  g_wbf[3 * 2 * 128 * 256];   // qkv W bf16 pre-swizzled
__device__ char  g_wep[6 * 32768];           // epilogue W panels

// ---------------- helpers ------------------------------------------------------
__device__ __forceinline__ uint32_t smem_u32(const void* p) {
    return (uint32_t)__cvta_generic_to_shared(p);
}
__device__ __forceinline__ void ldsm_x4(uint32_t* r, uint32_t addr) {
    asm volatile("ldmatrix.sync.aligned.m8n8.x4.shared.b16 {%0,%1,%2,%3}, [%4];\n"
                 : "=r"(r[0]), "=r"(r[1]), "=r"(r[2]), "=r"(r[3]) : "r"(addr));
}
__device__ __forceinline__ void ldsm_x4_t(uint32_t* r, uint32_t addr) {
    asm volatile("ldmatrix.sync.aligned.m8n8.x4.trans.shared.b16 {%0,%1,%2,%3}, [%4];\n"
                 : "=r"(r[0]), "=r"(r[1]), "=r"(r[2]), "=r"(r[3]) : "r"(addr));
}
__device__ __forceinline__ void mma_bf16(float* d, const uint32_t* a, uint32_t b0, uint32_t b1) {
    asm volatile("mma.sync.aligned.m16n8k16.row.col.f32.bf16.bf16.f32 "
                 "{%0,%1,%2,%3},{%4,%5,%6,%7},{%8,%9},{%0,%1,%2,%3};\n"
                 : "+f"(d[0]), "+f"(d[1]), "+f"(d[2]), "+f"(d[3])
                 : "r"(a[0]), "r"(a[1]), "r"(a[2]), "r"(a[3]), "r"(b0), "r"(b1));
}
__device__ __forceinline__ uint32_t packbf(float lo, float hi) {
    __nv_bfloat162 t = __floats2bfloat162_rn(lo, hi);
    return *(uint32_t*)&t;
}
__device__ __forceinline__ void cp16(uint32_t smem, const void* g) {
    asm volatile("cp.async.cg.shared.global [%0], [%1], 16;\n" :: "r"(smem), "l"(g));
}
__device__ __forceinline__ void cp_commit() {
    asm volatile("cp.async.commit_group;\n");
}
template<int N> __device__ __forceinline__ void cp_wait() {
    asm volatile("cp.async.wait_group %0;\n" :: "n"(N));
}
__device__ __forceinline__ float ex2(float x) {
    float r;
    asm("ex2.approx.ftz.f32 %0, %1;\n" : "=f"(r) : "f"(x));
    return r;
}

// 16 rows x 64 cols per warp, K=128 chunk
__device__ __forceinline__ void epi_gemm(float (*acc)[4], uint32_t a_base, uint32_t wb,
                                         int lane, int r0, int cb0) {
#pragma unroll
    for (int ks = 0; ks < 8; ks++) {
        uint32_t af[4];
        {
            int row = r0 + (lane & 7) + (((lane >> 3) & 1) << 3);
            int ch = 2 * ks + (lane >> 4);
            ldsm_x4(af, a_base + row * 256 + ((ch ^ (row & 7)) << 4));
        }
#pragma unroll
        for (int t = 0; t < 4; t++) {
            uint32_t bf[4];
            int krow = 16 * ks + (lane & 7) + (((lane >> 3) & 1) << 3);
            int ch = cb0 + 2 * t + (lane >> 4);
            ldsm_x4_t(bf, wb + krow * 256 + ((ch ^ (krow & 7)) << 4));
            mma_bf16(acc[2 * t], af, bf[0], bf[1]);
            mma_bf16(acc[2 * t + 1], af, bf[2], bf[3]);
        }
    }
}

// ---------------- prep: qkv W (0..191), mask (192) ----------------------------
__global__ void prep_kernel(const float* __restrict__ Wq,
                            const float* __restrict__ Wk,
                            const float* __restrict__ Wv,
                            const unsigned char* __restrict__ raw) {
    int tid = threadIdx.x;
    if (blockIdx.x < 192) {
        int i = blockIdx.x * 256 + tid;
        int mat = i >> 14, rem = i & 16383;
        int kk = rem >> 7, pp = rem & 127;
        int half = pp >> 6, p = pp & 63;
        const float* W = (mat == 0) ? Wq : (mat == 1) ? Wk : Wv;
        int c0 = half * 128 + 2 * p;
        uint32_t val = packbf(W[kk * MD + c0], W[kk * MD + c0 + 1]);
        char* dst = g_wbf + (((mat * 2 + half) * 128 + kk) * 256)
                    + ((((p >> 2) ^ (kk & 7))) << 4) + ((p & 3) << 2);
        *(uint32_t*)dst = val;
        return;
    }
    __shared__ int cnt_f, cnt_i;
    if (tid == 0) { cnt_f = 0; cnt_i = 0; }
    __syncthreads();
    const unsigned int* w = (const unsigned int*)raw;
    int fl = 0, il = 0;
    for (int i = tid; i < 1536; i += blockDim.x) {
        unsigned int x = w[i];
        fl += (x == 0x3F800000u || x == 0u);
        il += (x <= 1u);
    }
    atomicAdd(&cnt_f, fl);
    atomicAdd(&cnt_i, il);
    __syncthreads();
    int mode;
    if (cnt_f == 1536) mode = 0;
    else if (cnt_i == 1536) mode = 1;
    else mode = 2;
    for (int i = tid; i < NVIEW * QLEN; i += blockDim.x) {
        int n = i / QLEN, qq = i % QLEN;
        int src = qq * NVIEW + n;
        bool m;
        if (mode == 0)      m = (((const float*)raw)[src] != 0.0f);
        else if (mode == 1) m = (((const int*)raw)[src] != 0);
        else                m = (raw[src] != 0);
        g_maskb[i] = m ? 0.0f : -1e30f;
    }
}

// ---------------- LN + projection (+ epilogue-W conversion in extra blocks) ---
// grid (44, 6, 4): bx<36 = ln_proj tiles; bx>=36 = g_wep panel conversion
#define LNPROJ_SMEM (64*256 + 128*256 + 2048)
__global__ __launch_bounds__(256, 2) void ln_proj_tc_kernel(
        const float* __restrict__ srcq, const float* __restrict__ srck,
        const float* __restrict__ srcv,
        const float* __restrict__ lnqg, const float* __restrict__ lnqb,
        const float* __restrict__ lnkg, const float* __restrict__ lnkb,
        const float* __restrict__ lnvg, const float* __restrict__ lnvb,
        const float* __restrict__ bq, const float* __restrict__ bk,
        const float* __restrict__ bv,
        const float* __restrict__ Wp, const float* __restrict__ W1,
        const float* __restrict__ W2) {
    int bx = blockIdx.x;
    int tid = threadIdx.x;
    if (bx >= 36) {
        // ---- epilogue W panel conversion (192 unique CTAs x 256 pairs) ----
        int idx = (bx - 36) + 8 * (blockIdx.y + NVIEW * blockIdx.z);
        int j = idx * 256 + tid;                     // 0..49151
        int panel = j >> 13, rem = j & 8191;
        int kk = rem >> 6, p = rem & 63;
        float w0, w1;
        if (panel < 2) {
            int k = panel * 128 + kk;
            w0 = Wp[k * 128 + 2 * p]; w1 = Wp[k * 128 + 2 * p + 1];
        } else if (panel < 4) {
            int nc = panel - 2;
            w0 = W1[kk * 256 + nc * 128 + 2 * p]; w1 = W1[kk * 256 + nc * 128 + 2 * p + 1];
        } else {
            int k = (panel - 4) * 128 + kk;
            w0 = W2[k * 128 + 2 * p]; w1 = W2[k * 128 + 2 * p + 1];
        }
        char* dst = g_wep + panel * 32768 + kk * 256
                    + ((((p >> 2) ^ (kk & 7))) << 4) + ((p & 3) << 2);
        *(uint32_t*)dst = packbf(w0, w1);
        return;
    }

    extern __shared__ char smraw[];
    char* As = smraw;
    char* Bs = smraw + 64 * 256;
    float2* part = (float2*)(smraw + 64 * 256 + 128 * 256);
    uint32_t as_base = smem_u32(As);
    uint32_t bs_base = smem_u32(Bs);

    int sel, q0, R;
    const float *src, *lng, *lnb, *bias;
    if (bx < 16)      { sel = 0; q0 = bx << 6;        R = QLEN; src = srcq; lng = lnqg; lnb = lnqb; bias = bq; }
    else if (bx < 26) { sel = 1; q0 = (bx - 16) << 6; R = KLEN; src = srck; lng = lnkg; lnb = lnkb; bias = bk; }
    else              { sel = 2; q0 = (bx - 26) << 6; R = KLEN; src = srcv; lng = lnvg; lnb = lnvb; bias = bv; }
    const char* wsw = g_wbf + sel * 65536;

    int lane = tid & 31, w = tid >> 5;
    int b = blockIdx.z, n = blockIdx.y;

    for (int i = tid; i < 2048; i += 256)
        cp16(bs_base + i * 16, wsw + i * 16);
    cp_commit();

    int dg = tid >> 6, r = tid & 63;
    const float* sp = src + ((size_t)(b * NVIEW + n) * DMODEL) * R + q0;
    float x[32];
#pragma unroll
    for (int j = 0; j < 32; j++) x[j] = sp[(size_t)(dg * 32 + j) * R + r];

    float s = 0.f, sq = 0.f;
#pragma unroll
    for (int j = 0; j < 32; j++) { s += x[j]; sq = fmaf(x[j], x[j], sq); }
    part[r * 4 + dg] = make_float2(s, sq);
    __syncthreads();
    float2 p0 = part[r * 4 + 0], p1 = part[r * 4 + 1];
    float2 p2 = part[r * 4 + 2], p3 = part[r * 4 + 3];
    float tot = (p0.x + p1.x) + (p2.x + p3.x);
    float tsq = (p0.y + p1.y) + (p2.y + p3.y);
    float mean = tot * (1.0f / 128.0f);
    float var = tsq * (1.0f / 128.0f) - mean * mean;
    float rstd = rsqrtf(var + 1e-5f);

#pragma unroll
    for (int jp = 0; jp < 16; jp++) {
        int d0 = dg * 32 + 2 * jp;
        float y0 = (x[2 * jp] - mean) * rstd * lng[d0] + lnb[d0];
        float y1 = (x[2 * jp + 1] - mean) * rstd * lng[d0 + 1] + lnb[d0 + 1];
        int p = dg * 16 + jp;
        *(uint32_t*)(As + r * 256 + (((p >> 2) ^ (r & 7)) << 4) + ((p & 3) << 2)) =
            packbf(y0, y1);
    }

    int r0 = 16 * (w & 3);
    int colh = 64 * (w >> 2);
    int cb0 = colh >> 3;

    __nv_bfloat16* dst = (sel == 0) ? g_qh : (sel == 1) ? g_kh : g_vh;
    int NR = NVIEW * R;
    size_t bm_base = (size_t)b * MHEAD;

    for (int nc = 0; nc < 2; nc++) {
        cp_wait<0>();
        __syncthreads();

        float acc[8][4];
#pragma unroll
        for (int nb = 0; nb < 8; nb++)
#pragma unroll
            for (int i = 0; i < 4; i++) acc[nb][i] = 0.f;

#pragma unroll
        for (int ks = 0; ks < 8; ks++) {
            uint32_t af[4];
            {
                int row = r0 + (lane & 7) + (((lane >> 3) & 1) << 3);
                int ch = 2 * ks + (lane >> 4);
                ldsm_x4(af, as_base + row * 256 + ((ch ^ (row & 7)) << 4));
            }
#pragma unroll
            for (int t = 0; t < 4; t++) {
                uint32_t bf[4];
                int krow = 16 * ks + (lane & 7) + (((lane >> 3) & 1) << 3);
                int ch = cb0 + 2 * t + (lane >> 4);
                ldsm_x4_t(bf, bs_base + krow * 256 + ((ch ^ (krow & 7)) << 4));
                mma_bf16(acc[2 * t], af, bf[0], bf[1]);
                mma_bf16(acc[2 * t + 1], af, bf[2], bf[3]);
            }
        }

        if (nc == 0) {
            __syncthreads();
            for (int i = tid; i < 2048; i += 256)
                cp16(bs_base + i * 16, wsw + 32768 + i * 16);
            cp_commit();
        }

        int rA = q0 + r0 + (lane >> 2);
        int rB = rA + 8;
#pragma unroll
        for (int nb = 0; nb < 8; nb++) {
            int c = nc * 128 + colh + 8 * nb + 2 * (lane & 3);
            int m = c >> 6, dh = c & 63;
            float b0v = bias[c], b1v = bias[c + 1];
            size_t base = ((bm_base + m) * NR + (size_t)n * R);
            __nv_bfloat162 v0 = __floats2bfloat162_rn(acc[nb][0] + b0v, acc[nb][1] + b1v);
            __nv_bfloat162 v1 = __floats2bfloat162_rn(acc[nb][2] + b0v, acc[nb][3] + b1v);
            *(__nv_bfloat162*)&dst[(base + rA) * DH + dh] = v0;
            *(__nv_bfloat162*)&dst[(base + rB) * DH + dh] = v1;
        }
    }
}

// ---------------- attention: 32 rows/warp + double-buffered Q -----------------
// smem: Qs[2] 32KB + Ks[2] 16KB + Vs[2] 16KB = 64KB; 2 CTAs/SM.
#define ATT_SMEM (32768 + 16384 + 16384)
__global__ __launch_bounds__(128, 2) void attn_kernel() {
    extern __shared__ char attsm[];
    uint32_t qs_base = smem_u32(attsm);          // 2 x 16KB
    uint32_t ks_base = qs_base + 32768;          // 2 x 8KB
    uint32_t vs_base = qs_base + 49152;          // 2 x 8KB

    int tid = threadIdx.x, lane = tid & 31, w = tid >> 5;   // w in 0..3
    int bm = blockIdx.y, b = bm >> 2, m = bm & 3;
    int q0 = blockIdx.x * 128;
    int split = blockIdx.z;
    int n0 = split * 3;
    const float LOG2E = 1.44269504f;
    const float SCALE2 = 0.125f * LOG2E;

    const char* kroot = (const char*)(g_kh + (size_t)bm * KTOT * DH);
    const char* vroot = (const char*)(g_vh + (size_t)bm * KTOT * DH);
    const char* qroot = (const char*)(g_qh + ((size_t)(bm * NVIEW) * QLEN + q0) * DH);

    float o[2][8][4];
#pragma unroll
    for (int rg = 0; rg < 2; rg++)
#pragma unroll
        for (int nb = 0; nb < 8; nb++)
#pragma unroll
            for (int i = 0; i < 4; i++) o[rg][nb][i] = 0.f;
    float row_l[2][2] = {{0.f, 0.f}, {0.f, 0.f}};

    uint32_t qa[2][4][4];
    float bias[2][2];

    // prologue: Q(view n0) into qbuf0 + KV tile 0 (one group)
    {
        const char* qp = qroot + ((size_t)(n0 * QLEN) * DH) * 2;
#pragma unroll
        for (int it = 0; it < 8; it++) {
            int i = tid + it * 128;
            int rr = i >> 3, c = i & 7;
            cp16(qs_base + rr * 128 + ((c ^ (rr & 7)) << 4), qp + i * 16);
        }
        const char* kp = kroot + ((size_t)(n0 * KLEN) * DH) * 2;
        const char* vp = vroot + ((size_t)(n0 * KLEN) * DH) * 2;
#pragma unroll
        for (int it = 0; it < 4; it++) {
            int i = tid + it * 128;
            int rr = i >> 3, c = i & 7;
            int sw = rr * 128 + ((c ^ (rr & 7)) << 4);
            cp16(ks_base + sw, kp + i * 16);
            cp16(vs_base + sw, vp + i * 16);
        }
        cp_commit();
    }

    for (int t = 0; t < 30; t++) {
        int nv = t / 10, kt = t % 10;            // nv: local view 0..2
        int buf = (t & 1) * 8192;
        int qbuf = (nv & 1) * 16384;

        cp_wait<0>();                  // KV(t) [+ Q(view) from earlier] ready
        __syncthreads();

        if (kt == 0) {
            int n = n0 + nv;
#pragma unroll
            for (int rg = 0; rg < 2; rg++) {
#pragma unroll
                for (int ks = 0; ks < 4; ks++) {
                    int row = 32 * w + 16 * rg + (lane & 7) + (((lane >> 3) & 1) << 3);
                    int ch = 2 * ks + (lane >> 4);
                    ldsm_x4(qa[rg][ks], qs_base + qbuf + row * 128 + ((ch ^ (row & 7)) << 4));
                }
                bias[rg][0] = g_maskb[n * QLEN + q0 + 32 * w + 16 * rg + (lane >> 2)] * LOG2E;
                bias[rg][1] = g_maskb[n * QLEN + q0 + 32 * w + 16 * rg + (lane >> 2) + 8] * LOG2E;
            }
        }

        if (kt == 2 && nv < 2) {       // prefetch Q(next view) into alt buffer
            int qb2 = ((nv + 1) & 1) * 16384;
            const char* qp = qroot + ((size_t)((n0 + nv + 1) * QLEN) * DH) * 2;
#pragma unroll
            for (int it = 0; it < 8; it++) {
                int i = tid + it * 128;
                int rr = i >> 3, c = i & 7;
                cp16(qs_base + qb2 + rr * 128 + ((c ^ (rr & 7)) << 4), qp + i * 16);
            }
            cp_commit();
        }

        if (t < 29) {                  // prefetch KV(t+1)
            int tn = t + 1;
            int nn = n0 + tn / 10, nkt = tn % 10;
            int nbuf = (tn & 1) * 8192;
            const char* kp = kroot + ((size_t)(nn * KLEN + nkt * 64) * DH) * 2;
            const char* vp = vroot + ((size_t)(nn * KLEN + nkt * 64) * DH) * 2;
#pragma unroll
            for (int it = 0; it < 4; it++) {
                int i = tid + it * 128;
                int rr = i >> 3, c = i & 7;
                int sw = rr * 128 + ((c ^ (rr & 7)) << 4);
                cp16(ks_base + nbuf + sw, kp + i * 16);
                cp16(vs_base + nbuf + sw, vp + i * 16);
            }
            cp_commit();
        }

        // ---- S = Q K^T : each B-frag feeds 4 mma ----
        float s[2][8][4];
#pragma unroll
        for (int rg = 0; rg < 2; rg++)
#pragma unroll
            for (int nb = 0; nb < 8; nb++)
#pragma unroll
                for (int i = 0; i < 4; i++) s[rg][nb][i] = 0.f;
#pragma unroll
        for (int ks = 0; ks < 4; ks++) {
#pragma unroll
            for (int tt = 0; tt < 4; tt++) {
                uint32_t bf[4];
                int key = 16 * tt + (lane & 7) + ((lane >> 4) << 3);
                int ch = 2 * ks + ((lane >> 3) & 1);
                ldsm_x4(bf, ks_base + buf + key * 128 + ((ch ^ (key & 7)) << 4));
                mma_bf16(s[0][2 * tt], qa[0][ks], bf[0], bf[1]);
                mma_bf16(s[0][2 * tt + 1], qa[0][ks], bf[2], bf[3]);
                mma_bf16(s[1][2 * tt], qa[1][ks], bf[0], bf[1]);
                mma_bf16(s[1][2 * tt + 1], qa[1][ks], bf[2], bf[3]);
            }
        }

        // ---- fixed-base softmax ----
#pragma unroll
        for (int rg = 0; rg < 2; rg++) {
            float sum0 = 0.f, sum1 = 0.f;
#pragma unroll
            for (int nb = 0; nb < 8; nb++) {
                s[rg][nb][0] = ex2(fmaf(s[rg][nb][0], SCALE2, bias[rg][0]));
                s[rg][nb][1] = ex2(fmaf(s[rg][nb][1], SCALE2, bias[rg][0]));
                s[rg][nb][2] = ex2(fmaf(s[rg][nb][2], SCALE2, bias[rg][1]));
                s[rg][nb][3] = ex2(fmaf(s[rg][nb][3], SCALE2, bias[rg][1]));
                sum0 += s[rg][nb][0] + s[rg][nb][1];
                sum1 += s[rg][nb][2] + s[rg][nb][3];
            }
            row_l[rg][0] += sum0;
            row_l[rg][1] += sum1;
        }

        // ---- O += P V ----
#pragma unroll
        for (int ks = 0; ks < 4; ks++) {
            uint32_t pa[2][4];
#pragma unroll
            for (int rg = 0; rg < 2; rg++) {
                pa[rg][0] = packbf(s[rg][2 * ks][0], s[rg][2 * ks][1]);
                pa[rg][1] = packbf(s[rg][2 * ks][2], s[rg][2 * ks][3]);
                pa[rg][2] = packbf(s[rg][2 * ks + 1][0], s[rg][2 * ks + 1][1]);
                pa[rg][3] = packbf(s[rg][2 * ks + 1][2], s[rg][2 * ks + 1][3]);
            }
#pragma unroll
            for (int tt = 0; tt < 4; tt++) {
                uint32_t bf[4];
                int key = 16 * ks + (lane & 7) + (((lane >> 3) & 1) << 3);
                int ch = 2 * tt + (lane >> 4);
                ldsm_x4_t(bf, vs_base + buf + key * 128 + ((ch ^ (key & 7)) << 4));
                mma_bf16(o[0][2 * tt], pa[0], bf[0], bf[1]);
                mma_bf16(o[0][2 * tt + 1], pa[0], bf[2], bf[3]);
                mma_bf16(o[1][2 * tt], pa[1], bf[0], bf[1]);
                mma_bf16(o[1][2 * tt + 1], pa[1], bf[2], bf[3]);
            }
        }
    }

    // ---- finish l + write partials ----
#pragma unroll
    for (int rg = 0; rg < 2; rg++) {
        float l0 = row_l[rg][0], l1 = row_l[rg][1];
        l0 += __shfl_xor_sync(0xffffffffu, l0, 1);
        l0 += __shfl_xor_sync(0xffffffffu, l0, 2);
        l1 += __shfl_xor_sync(0xffffffffu, l1, 1);
        l1 += __shfl_xor_sync(0xffffffffu, l1, 2);

        int row0 = q0 + 32 * w + 16 * rg + (lane >> 2);
        float* po = g_po[split] + ((size_t)b * QLEN) * MD;
#pragma unroll
        for (int nb = 0; nb < 8; nb++) {
            int dh = 8 * nb + 2 * (lane & 3);
            *(float2*)(po + (size_t)row0 * MD + m * DH + dh) =
                make_float2(o[rg][nb][0], o[rg][nb][1]);
            *(float2*)(po + (size_t)(row0 + 8) * MD + m * DH + dh) =
                make_float2(o[rg][nb][2], o[rg][nb][3]);
        }
        if ((lane & 3) == 0) {
            g_pl[split][bm * QLEN + row0] = l0;
            g_pl[split][bm * QLEN + row0 + 8] = l1;
        }
    }
}

// ---------------- epilogue: tensor-core, panel-streamed (frozen) ---------------
__device__ __forceinline__ void ln_stats128(const float* row, int lane,
                                            float& mean, float& rstd) {
    float s = 0.f;
#pragma unroll
    for (int kk = 0; kk < 4; kk++) s += row[lane + 32 * kk];
#pragma unroll
    for (int o = 16; o; o >>= 1) s += __shfl_xor_sync(0xffffffffu, s, o);
    mean = s * (1.0f / 128.0f);
    float vv = 0.f;
#pragma unroll
    for (int kk = 0; kk < 4; kk++) { float t = row[lane + 32 * kk] - mean; vv += t * t; }
#pragma unroll
    for (int o = 16; o; o >>= 1) vv += __shfl_xor_sync(0xffffffffu, vv, o);
    rstd = rsqrtf(vv * (1.0f / 128.0f) + 1e-5f);
}

#define EPI_SMEM (16384 + 8192*3 + 32768*2)
__global__ __launch_bounds__(128, 2) void epilogue_kernel(
        const float* __restrict__ skip, const float* __restrict__ bp,
        const float* __restrict__ preg, const float* __restrict__ preb,
        const float* __restrict__ b1, const float* __restrict__ b2,
        const float* __restrict__ postg, const float* __restrict__ postb,
        float* __restrict__ out) {
    extern __shared__ char esm[];
    float* Zs = (float*)esm;
    char* P0 = esm + 16384;
    char* P1 = esm + 24576;
    char* Zb = esm + 32768;
    uint32_t p0_base = smem_u32(P0), p1_base = smem_u32(P1), zb_base = smem_u32(Zb);
    uint32_t wb0 = smem_u32(esm + 40960), wb1 = smem_u32(esm + 73728);

    int tid = threadIdx.x, lane = tid & 31, w = tid >> 5;
    int b = blockIdx.y, q0 = blockIdx.x * 32;
    int r0 = 16 * (w & 1), colh = 64 * (w >> 1), cb0 = colh >> 3;
    int rA = r0 + (lane >> 2), rB = rA + 8;

    for (int i = tid; i < 2048; i += 128) cp16(wb0 + i * 16, g_wep + i * 16);
    cp_commit();

    for (int i = tid; i < 32 * 64; i += 128) {
        int row = i >> 6, c4 = i & 63;
        int q = q0 + row, m = c4 >> 4;
        float l = g_pl[0][(b * 4 + m) * QLEN + q] + g_pl[1][(b * 4 + m) * QLEN + q];
        float inv = 1.0f / l;
        size_t off = ((size_t)(b * QLEN + q)) * MD + c4 * 4;
        float4 a0 = *(const float4*)(g_po[0] + off);
        float4 a1 = *(const float4*)(g_po[1] + off);
        char* pan = (c4 < 32) ? P0 : P1;
        int pl = (c4 * 2) & 63;
        uint32_t v0 = packbf((a0.x + a1.x) * inv, (a0.y + a1.y) * inv);
        uint32_t v1 = packbf((a0.z + a1.z) * inv, (a0.w + a1.w) * inv);
        *(uint32_t*)(pan + row * 256 + (((pl >> 2) ^ (row & 7)) << 4) + ((pl & 3) << 2)) = v0;
        int pl1 = pl + 1;
        *(uint32_t*)(pan + row * 256 + (((pl1 >> 2) ^ (row & 7)) << 4) + ((pl1 & 3) << 2)) = v1;
    }

    for (int i = tid; i < 2048; i += 128) cp16(wb1 + i * 16, g_wep + 32768 + i * 16);
    cp_commit();
    __syncthreads();

    float acc[8][4];
#pragma unroll
    for (int nb = 0; nb < 8; nb++)
#pragma unroll
        for (int i = 0; i < 4; i++) acc[nb][i] = 0.f;

    cp_wait<1>(); __syncthreads();
    epi_gemm(acc, p0_base, wb0, lane, r0, cb0);
    __syncthreads();
    for (int i = tid; i < 2048; i += 128) cp16(wb0 + i * 16, g_wep + 2 * 32768 + i * 16);
    cp_commit();
    cp_wait<1>(); __syncthreads();
    epi_gemm(acc, p1_base, wb1, lane, r0, cb0);

#pragma unroll
    for (int nb = 0; nb < 8; nb++) {
        int c = colh + 8 * nb + 2 * (lane & 3);
        Zs[rA * 128 + c]     = acc[nb][0] + bp[c]     + skip[((size_t)b * 128 + c) * 1024 + q0 + rA];
        Zs[rA * 128 + c + 1] = acc[nb][1] + bp[c + 1] + skip[((size_t)b * 128 + c + 1) * 1024 + q0 + rA];
        Zs[rB * 128 + c]     = acc[nb][2] + bp[c]     + skip[((size_t)b * 128 + c) * 1024 + q0 + rB];
        Zs[rB * 128 + c + 1] = acc[nb][3] + bp[c + 1] + skip[((size_t)b * 128 + c + 1) * 1024 + q0 + rB];
    }
    __syncthreads();
    for (int i = tid; i < 2048; i += 128) cp16(wb1 + i * 16, g_wep + 3 * 32768 + i * 16);
    cp_commit();

#pragma unroll
    for (int rr = 0; rr < 8; rr++) {
        int r = w * 8 + rr;
        float mean, rstd;
        ln_stats128(&Zs[r * 128], lane, mean, rstd);
        int d0 = 2 * lane, d1 = 64 + 2 * lane;
        float z0 = (Zs[r * 128 + d0] - mean) * rstd * preg[d0] + preb[d0];
        float z1 = (Zs[r * 128 + d0 + 1] - mean) * rstd * preg[d0 + 1] + preb[d0 + 1];
        float z2 = (Zs[r * 128 + d1] - mean) * rstd * preg[d1] + preb[d1];
        float z3 = (Zs[r * 128 + d1 + 1] - mean) * rstd * preg[d1 + 1] + preb[d1 + 1];
        __syncwarp();
        Zs[r * 128 + d0] = z0; Zs[r * 128 + d0 + 1] = z1;
        Zs[r * 128 + d1] = z2; Zs[r * 128 + d1 + 1] = z3;
        int p = lane, p2 = lane + 32;
        *(uint32_t*)(Zb + r * 256 + (((p >> 2) ^ (r & 7)) << 4) + ((p & 3) << 2)) = packbf(z0, z1);
        *(uint32_t*)(Zb + r * 256 + (((p2 >> 2) ^ (r & 7)) << 4) + ((p2 & 3) << 2)) = packbf(z2, z3);
    }
    __syncthreads();

    cp_wait<1>(); __syncthreads();
    {
        float a2[8][4];
#pragma unroll
        for (int nb = 0; nb < 8; nb++)
#pragma unroll
            for (int i = 0; i < 4; i++) a2[nb][i] = 0.f;
        epi_gemm(a2, zb_base, wb0, lane, r0, cb0);
#pragma unroll
        for (int nb = 0; nb < 8; nb++) {
            int cl = colh + 8 * nb + 2 * (lane & 3);
            float x0 = a2[nb][0] + b1[cl],     x1 = a2[nb][1] + b1[cl + 1];
            float x2 = a2[nb][2] + b1[cl],     x3 = a2[nb][3] + b1[cl + 1];
            x0 = 0.5f * x0 * (1.0f + erff(x0 * 0.70710678118f));
            x1 = 0.5f * x1 * (1.0f + erff(x1 * 0.70710678118f));
            x2 = 0.5f * x2 * (1.0f + erff(x2 * 0.70710678118f));
            x3 = 0.5f * x3 * (1.0f + erff(x3 * 0.70710678118f));
            int pl = cl >> 1;
            *(uint32_t*)(P0 + rA * 256 + (((pl >> 2) ^ (rA & 7)) << 4) + ((pl & 3) << 2)) = packbf(x0, x1);
            *(uint32_t*)(P0 + rB * 256 + (((pl >> 2) ^ (rB & 7)) << 4) + ((pl & 3) << 2)) = packbf(x2, x3);
        }
    }
    __syncthreads();
    for (int i = tid; i < 2048; i += 128) cp16(wb0 + i * 16, g_wep + 4 * 32768 + i * 16);
    cp_commit();
    cp_wait<1>(); __syncthreads();
    {
        float a2[8][4];
#pragma unroll
        for (int nb = 0; nb < 8; nb++)
#pragma unroll
            for (int i = 0; i < 4; i++) a2[nb][i] = 0.f;
        epi_gemm(a2, zb_base, wb1, lane, r0, cb0);
#pragma unroll
        for (int nb = 0; nb < 8; nb++) {
            int cl = colh + 8 * nb + 2 * (lane & 3);
            float x0 = a2[nb][0] + b1[128 + cl],     x1 = a2[nb][1] + b1[128 + cl + 1];
            float x2 = a2[nb][2] + b1[128 + cl],     x3 = a2[nb][3] + b1[128 + cl + 1];
            x0 = 0.5f * x0 * (1.0f + erff(x0 * 0.70710678118f));
            x1 = 0.5f * x1 * (1.0f + erff(x1 * 0.70710678118f));
            x2 = 0.5f * x2 * (1.0f + erff(x2 * 0.70710678118f));
            x3 = 0.5f * x3 * (1.0f + erff(x3 * 0.70710678118f));
            int pl = cl >> 1;
            *(uint32_t*)(P1 + rA * 256 + (((pl >> 2) ^ (rA & 7)) << 4) + ((pl & 3) << 2)) = packbf(x0, x1);
            *(uint32_t*)(P1 + rB * 256 + (((pl >> 2) ^ (rB & 7)) << 4) + ((pl & 3) << 2)) = packbf(x2, x3);
        }
    }
    __syncthreads();
    for (int i = tid; i < 2048; i += 128) cp16(wb1 + i * 16, g_wep + 5 * 32768 + i * 16);
    cp_commit();

    float a3[8][4];
#pragma unroll
    for (int nb = 0; nb < 8; nb++)
#pragma unroll
        for (int i = 0; i < 4; i++) a3[nb][i] = 0.f;
    cp_wait<1>(); __syncthreads();
    epi_gemm(a3, p0_base, wb0, lane, r0, cb0);
    cp_wait<0>(); __syncthreads();
    epi_gemm(a3, p1_base, wb1, lane, r0, cb0);

#pragma unroll
    for (int nb = 0; nb < 8; nb++) {
        int c = colh + 8 * nb + 2 * (lane & 3);
        Zs[rA * 128 + c]     = a3[nb][0] + b2[c]     + Zs[rA * 128 + c];
        Zs[rA * 128 + c + 1] = a3[nb][1] + b2[c + 1] + Zs[rA * 128 + c + 1];
        Zs[rB * 128 + c]     = a3[nb][2] + b2[c]     + Zs[rB * 128 + c];
        Zs[rB * 128 + c + 1] = a3[nb][3] + b2[c + 1] + Zs[rB * 128 + c + 1];
    }
    __syncthreads();

#pragma unroll
    for (int rr = 0; rr < 8; rr++) {
        int r = w * 8 + rr;
        float mean, rstd;
        ln_stats128(&Zs[r * 128], lane, mean, rstd);
        int q = q0 + r;
#pragma unroll
        for (int kk = 0; kk < 4; kk++) {
            int d = lane + 32 * kk;
            float val = (Zs[r * 128 + d] - mean) * rstd * postg[d] + postb[d];
            out[((size_t)b * 128 + d) * 1024 + q] = val;
        }
    }
}

// ---------------- launch -------------------------------------------------------
extern "C" void kernel_launch(void* const* d_in, const int* in_sizes, int n_in,
                              void* d_out, int out_size) {
    const float* q    = (const float*)d_in[0];
    const float* k    = (const float*)d_in[1];
    const float* v    = (const float*)d_in[2];
    const float* skip = (const float*)d_in[3];
    const unsigned char* mask = (const unsigned char*)d_in[4];
    const float* lnq_g = (const float*)d_in[5];
    const float* lnq_b = (const float*)d_in[6];
    const float* lnk_g = (const float*)d_in[7];
    const float* lnk_b = (const float*)d_in[8];
    const float* lnv_g = (const float*)d_in[9];
    const float* lnv_b = (const float*)d_in[10];
    const float* Wq = (const float*)d_in[11];
    const float* bq = (const float*)d_in[12];
    const float* Wk = (const float*)d_in[13];
    const float* bk = (const float*)d_in[14];
    const float* Wv = (const float*)d_in[15];
    const float* bv = (const float*)d_in[16];
    const float* Wp = (const float*)d_in[17];
    const float* bp = (const float*)d_in[18];
    const float* pre_g = (const float*)d_in[19];
    const float* pre_b = (const float*)d_in[20];
    const float* W1 = (const float*)d_in[21];
    const float* b1 = (const float*)d_in[22];
    const float* W2 = (const float*)d_in[23];
    const float* b2 = (const float*)d_in[24];
    const float* post_g = (const float*)d_in[25];
    const float* post_b = (const float*)d_in[26];
    float* out = (float*)d_out;

    cudaFuncSetAttribute(ln_proj_tc_kernel, cudaFuncAttributeMaxDynamicSharedMemorySize, LNPROJ_SMEM);
    cudaFuncSetAttribute(attn_kernel, cudaFuncAttributeMaxDynamicSharedMemorySize, ATT_SMEM);
    cudaFuncSetAttribute(epilogue_kernel, cudaFuncAttributeMaxDynamicSharedMemorySize, EPI_SMEM);

    prep_kernel<<<193, 256>>>(Wq, Wk, Wv, mask);
    ln_proj_tc_kernel<<<dim3(44, NVIEW, BATCH), 256, LNPROJ_SMEM>>>(
        q, k, v, lnq_g, lnq_b, lnk_g, lnk_b, lnv_g, lnv_b, bq, bk, bv, Wp, W1, W2);
    attn_kernel<<<dim3(8, 16, 2), 128, ATT_SMEM>>>();
    epilogue_kernel<<<dim3(32, BATCH), 128, EPI_SMEM>>>(skip, bp, pre_g, pre_b,
                                                        b1, b2, post_g, post_b, out);
}

// round 17
// speedup vs baseline: 1.0819x; 1.0819x over previous
#include <cuda_runtime.h>
#include <cuda_bf16.h>
#include <cstdint>
#include <math.h>

#define BATCH 4
#define NVIEW 6
#define DMODEL 128
#define QLEN 1024
#define KLEN 640
#define MHEAD 4
#define DH 64
#define MD 256
#define KTOT (NVIEW*KLEN)   // 3840
#define BM (BATCH*MHEAD)    // 16

// ---------------- scratch (device globals; no allocation allowed) -------------
__device__ __nv_bfloat16 g_qh[BM * NVIEW * QLEN * DH];
__device__ __nv_bfloat16 g_kh[BM * KTOT * DH];
__device__ __nv_bfloat16 g_vh[BM * KTOT * DH];
__device__ __nv_bfloat16 g_po[2][BATCH * QLEN * MD];   // bf16 unnormalized partials
__device__ float g_pl[2][BM * QLEN];
__device__ float g_maskb[NVIEW * QLEN];
__device__ char  g_wbf[3 * 2 * 128 * 256];   // qkv W bf16 pre-swizzled
__device__ char  g_wep[6 * 32768];           // epilogue W panels

// ---------------- helpers ------------------------------------------------------
__device__ __forceinline__ uint32_t smem_u32(const void* p) {
    return (uint32_t)__cvta_generic_to_shared(p);
}
__device__ __forceinline__ void ldsm_x4(uint32_t* r, uint32_t addr) {
    asm volatile("ldmatrix.sync.aligned.m8n8.x4.shared.b16 {%0,%1,%2,%3}, [%4];\n"
                 : "=r"(r[0]), "=r"(r[1]), "=r"(r[2]), "=r"(r[3]) : "r"(addr));
}
__device__ __forceinline__ void ldsm_x4_t(uint32_t* r, uint32_t addr) {
    asm volatile("ldmatrix.sync.aligned.m8n8.x4.trans.shared.b16 {%0,%1,%2,%3}, [%4];\n"
                 : "=r"(r[0]), "=r"(r[1]), "=r"(r[2]), "=r"(r[3]) : "r"(addr));
}
__device__ __forceinline__ void mma_bf16(float* d, const uint32_t* a, uint32_t b0, uint32_t b1) {
    asm volatile("mma.sync.aligned.m16n8k16.row.col.f32.bf16.bf16.f32 "
                 "{%0,%1,%2,%3},{%4,%5,%6,%7},{%8,%9},{%0,%1,%2,%3};\n"
                 : "+f"(d[0]), "+f"(d[1]), "+f"(d[2]), "+f"(d[3])
                 : "r"(a[0]), "r"(a[1]), "r"(a[2]), "r"(a[3]), "r"(b0), "r"(b1));
}
__device__ __forceinline__ uint32_t packbf(float lo, float hi) {
    __nv_bfloat162 t = __floats2bfloat162_rn(lo, hi);
    return *(uint32_t*)&t;
}
__device__ __forceinline__ float2 bf2f(uint32_t v) {
    return __bfloat1622float2(*(__nv_bfloat162*)&v);
}
__device__ __forceinline__ void cp16(uint32_t smem, const void* g) {
    asm volatile("cp.async.cg.shared.global [%0], [%1], 16;\n" :: "r"(smem), "l"(g));
}
__device__ __forceinline__ void cp_commit() {
    asm volatile("cp.async.commit_group;\n");
}
template<int N> __device__ __forceinline__ void cp_wait() {
    asm volatile("cp.async.wait_group %0;\n" :: "n"(N));
}
__device__ __forceinline__ float ex2(float x) {
    float r;
    asm("ex2.approx.ftz.f32 %0, %1;\n" : "=f"(r) : "f"(x));
    return r;
}

// 16 rows x 32 cols per warp, K=128 chunk (epilogue variant)
__device__ __forceinline__ void epi_gemm16(float (*acc)[4], uint32_t a_base, uint32_t wb,
                                           int lane, int cb0) {
#pragma unroll
    for (int ks = 0; ks < 8; ks++) {
        uint32_t af[4];
        {
            int row = (lane & 7) + (((lane >> 3) & 1) << 3);
            int ch = 2 * ks + (lane >> 4);
            ldsm_x4(af, a_base + row * 256 + ((ch ^ (row & 7)) << 4));
        }
#pragma unroll
        for (int t = 0; t < 2; t++) {
            uint32_t bf[4];
            int krow = 16 * ks + (lane & 7) + (((lane >> 3) & 1) << 3);
            int ch = cb0 + 2 * t + (lane >> 4);
            ldsm_x4_t(bf, wb + krow * 256 + ((ch ^ (krow & 7)) << 4));
            mma_bf16(acc[2 * t], af, bf[0], bf[1]);
            mma_bf16(acc[2 * t + 1], af, bf[2], bf[3]);
        }
    }
}

// ---------------- prep: qkv W (0..191), mask (192), epilogue W (193..384) -----
__global__ void prep_kernel(const float* __restrict__ Wq,
                            const float* __restrict__ Wk,
                            const float* __restrict__ Wv,
                            const float* __restrict__ Wp,
                            const float* __restrict__ W1,
                            const float* __restrict__ W2,
                            const unsigned char* __restrict__ raw) {
    int tid = threadIdx.x;
    if (blockIdx.x < 192) {
        int i = blockIdx.x * 256 + tid;
        int mat = i >> 14, rem = i & 16383;
        int kk = rem >> 7, pp = rem & 127;
        int half = pp >> 6, p = pp & 63;
        const float* W = (mat == 0) ? Wq : (mat == 1) ? Wk : Wv;
        int c0 = half * 128 + 2 * p;
        uint32_t val = packbf(W[kk * MD + c0], W[kk * MD + c0 + 1]);
        char* dst = g_wbf + (((mat * 2 + half) * 128 + kk) * 256)
                    + ((((p >> 2) ^ (kk & 7))) << 4) + ((p & 3) << 2);
        *(uint32_t*)dst = val;
        return;
    }
    if (blockIdx.x >= 193) {
        int j = (blockIdx.x - 193) * 256 + tid;
        int panel = j >> 13, rem = j & 8191;
        int kk = rem >> 6, p = rem & 63;
        float w0, w1;
        if (panel < 2) {
            int k = panel * 128 + kk;
            w0 = Wp[k * 128 + 2 * p]; w1 = Wp[k * 128 + 2 * p + 1];
        } else if (panel < 4) {
            int nc = panel - 2;
            w0 = W1[kk * 256 + nc * 128 + 2 * p]; w1 = W1[kk * 256 + nc * 128 + 2 * p + 1];
        } else {
            int k = (panel - 4) * 128 + kk;
            w0 = W2[k * 128 + 2 * p]; w1 = W2[k * 128 + 2 * p + 1];
        }
        char* dst = g_wep + panel * 32768 + kk * 256
                    + ((((p >> 2) ^ (kk & 7))) << 4) + ((p & 3) << 2);
        *(uint32_t*)dst = packbf(w0, w1);
        return;
    }
    __shared__ int cnt_f, cnt_i;
    if (tid == 0) { cnt_f = 0; cnt_i = 0; }
    __syncthreads();
    const unsigned int* w = (const unsigned int*)raw;
    int fl = 0, il = 0;
    for (int i = tid; i < 1536; i += blockDim.x) {
        unsigned int x = w[i];
        fl += (x == 0x3F800000u || x == 0u);
        il += (x <= 1u);
    }
    atomicAdd(&cnt_f, fl);
    atomicAdd(&cnt_i, il);
    __syncthreads();
    int mode;
    if (cnt_f == 1536) mode = 0;
    else if (cnt_i == 1536) mode = 1;
    else mode = 2;
    for (int i = tid; i < NVIEW * QLEN; i += blockDim.x) {
        int n = i / QLEN, qq = i % QLEN;
        int src = qq * NVIEW + n;
        bool m;
        if (mode == 0)      m = (((const float*)raw)[src] != 0.0f);
        else if (mode == 1) m = (((const int*)raw)[src] != 0);
        else                m = (raw[src] != 0);
        g_maskb[i] = m ? 0.0f : -1e30f;
    }
}

// ---------------- LN + projection (R13/R14 version, frozen) -------------------
#define LNPROJ_SMEM (64*256 + 128*256 + 2048)
__global__ __launch_bounds__(256, 2) void ln_proj_tc_kernel(
        const float* __restrict__ srcq, const float* __restrict__ srck,
        const float* __restrict__ srcv,
        const float* __restrict__ lnqg, const float* __restrict__ lnqb,
        const float* __restrict__ lnkg, const float* __restrict__ lnkb,
        const float* __restrict__ lnvg, const float* __restrict__ lnvb,
        const float* __restrict__ bq, const float* __restrict__ bk,
        const float* __restrict__ bv) {
    extern __shared__ char smraw[];
    char* As = smraw;
    char* Bs = smraw + 64 * 256;
    float2* part = (float2*)(smraw + 64 * 256 + 128 * 256);
    uint32_t as_base = smem_u32(As);
    uint32_t bs_base = smem_u32(Bs);

    int bx = blockIdx.x;
    int sel, q0, R;
    const float *src, *lng, *lnb, *bias;
    if (bx < 16)      { sel = 0; q0 = bx << 6;        R = QLEN; src = srcq; lng = lnqg; lnb = lnqb; bias = bq; }
    else if (bx < 26) { sel = 1; q0 = (bx - 16) << 6; R = KLEN; src = srck; lng = lnkg; lnb = lnkb; bias = bk; }
    else              { sel = 2; q0 = (bx - 26) << 6; R = KLEN; src = srcv; lng = lnvg; lnb = lnvb; bias = bv; }
    const char* wsw = g_wbf + sel * 65536;

    int tid = threadIdx.x, lane = tid & 31, w = tid >> 5;
    int b = blockIdx.z, n = blockIdx.y;

    for (int i = tid; i < 2048; i += 256)
        cp16(bs_base + i * 16, wsw + i * 16);
    cp_commit();

    int dg = tid >> 6, r = tid & 63;
    const float* sp = src + ((size_t)(b * NVIEW + n) * DMODEL) * R + q0;
    float x[32];
#pragma unroll
    for (int j = 0; j < 32; j++) x[j] = sp[(size_t)(dg * 32 + j) * R + r];

    float s = 0.f, sq = 0.f;
#pragma unroll
    for (int j = 0; j < 32; j++) { s += x[j]; sq = fmaf(x[j], x[j], sq); }
    part[r * 4 + dg] = make_float2(s, sq);
    __syncthreads();
    float2 p0 = part[r * 4 + 0], p1 = part[r * 4 + 1];
    float2 p2 = part[r * 4 + 2], p3 = part[r * 4 + 3];
    float tot = (p0.x + p1.x) + (p2.x + p3.x);
    float tsq = (p0.y + p1.y) + (p2.y + p3.y);
    float mean = tot * (1.0f / 128.0f);
    float var = tsq * (1.0f / 128.0f) - mean * mean;
    float rstd = rsqrtf(var + 1e-5f);

#pragma unroll
    for (int jp = 0; jp < 16; jp++) {
        int d0 = dg * 32 + 2 * jp;
        float y0 = (x[2 * jp] - mean) * rstd * lng[d0] + lnb[d0];
        float y1 = (x[2 * jp + 1] - mean) * rstd * lng[d0 + 1] + lnb[d0 + 1];
        int p = dg * 16 + jp;
        *(uint32_t*)(As + r * 256 + (((p >> 2) ^ (r & 7)) << 4) + ((p & 3) << 2)) =
            packbf(y0, y1);
    }

    int r0 = 16 * (w & 3);
    int colh = 64 * (w >> 2);
    int cb0 = colh >> 3;

    __nv_bfloat16* dst = (sel == 0) ? g_qh : (sel == 1) ? g_kh : g_vh;
    int NR = NVIEW * R;
    size_t bm_base = (size_t)b * MHEAD;

    for (int nc = 0; nc < 2; nc++) {
        cp_wait<0>();
        __syncthreads();

        float acc[8][4];
#pragma unroll
        for (int nb = 0; nb < 8; nb++)
#pragma unroll
            for (int i = 0; i < 4; i++) acc[nb][i] = 0.f;

#pragma unroll
        for (int ks = 0; ks < 8; ks++) {
            uint32_t af[4];
            {
                int row = r0 + (lane & 7) + (((lane >> 3) & 1) << 3);
                int ch = 2 * ks + (lane >> 4);
                ldsm_x4(af, as_base + row * 256 + ((ch ^ (row & 7)) << 4));
            }
#pragma unroll
            for (int t = 0; t < 4; t++) {
                uint32_t bf[4];
                int krow = 16 * ks + (lane & 7) + (((lane >> 3) & 1) << 3);
                int ch = cb0 + 2 * t + (lane >> 4);
                ldsm_x4_t(bf, bs_base + krow * 256 + ((ch ^ (krow & 7)) << 4));
                mma_bf16(acc[2 * t], af, bf[0], bf[1]);
                mma_bf16(acc[2 * t + 1], af, bf[2], bf[3]);
            }
        }

        if (nc == 0) {
            __syncthreads();
            for (int i = tid; i < 2048; i += 256)
                cp16(bs_base + i * 16, wsw + 32768 + i * 16);
            cp_commit();
        }

        int rA = q0 + r0 + (lane >> 2);
        int rB = rA + 8;
#pragma unroll
        for (int nb = 0; nb < 8; nb++) {
            int c = nc * 128 + colh + 8 * nb + 2 * (lane & 3);
            int m = c >> 6, dh = c & 63;
            float b0v = bias[c], b1v = bias[c + 1];
            size_t base = ((bm_base + m) * NR + (size_t)n * R);
            __nv_bfloat162 v0 = __floats2bfloat162_rn(acc[nb][0] + b0v, acc[nb][1] + b1v);
            __nv_bfloat162 v1 = __floats2bfloat162_rn(acc[nb][2] + b0v, acc[nb][3] + b1v);
            *(__nv_bfloat162*)&dst[(base + rA) * DH + dh] = v0;
            *(__nv_bfloat162*)&dst[(base + rB) * DH + dh] = v1;
        }
    }
}

// ---------------- attention: 32 rows/warp (R14 version), bf16 partials --------
#define ATT_SMEM (16384 + 16384 + 16384)
__global__ __launch_bounds__(128, 2) void attn_kernel() {
    extern __shared__ char attsm[];
    uint32_t qs_base = smem_u32(attsm);
    uint32_t ks_base = qs_base + 16384;
    uint32_t vs_base = qs_base + 32768;

    int tid = threadIdx.x, lane = tid & 31, w = tid >> 5;
    int bm = blockIdx.y, b = bm >> 2, m = bm & 3;
    int q0 = blockIdx.x * 128;
    int split = blockIdx.z;
    int n0 = split * 3;
    const float LOG2E = 1.44269504f;
    const float SCALE2 = 0.125f * LOG2E;

    const char* kroot = (const char*)(g_kh + (size_t)bm * KTOT * DH);
    const char* vroot = (const char*)(g_vh + (size_t)bm * KTOT * DH);

    float o[2][8][4];
#pragma unroll
    for (int rg = 0; rg < 2; rg++)
#pragma unroll
        for (int nb = 0; nb < 8; nb++)
#pragma unroll
            for (int i = 0; i < 4; i++) o[rg][nb][i] = 0.f;
    float row_l[2][2] = {{0.f, 0.f}, {0.f, 0.f}};

    uint32_t qa[2][4][4];
    float bias[2][2];

    {
        const char* kp = kroot + ((size_t)(n0 * KLEN) * DH) * 2;
        const char* vp = vroot + ((size_t)(n0 * KLEN) * DH) * 2;
#pragma unroll
        for (int it = 0; it < 4; it++) {
            int i = tid + it * 128;
            int rr = i >> 3, c = i & 7;
            int sw = rr * 128 + ((c ^ (rr & 7)) << 4);
            cp16(ks_base + sw, kp + i * 16);
            cp16(vs_base + sw, vp + i * 16);
        }
        cp_commit();
    }

    for (int t = 0; t < 30; t++) {
        int nv = t / 10, kt = t % 10;
        int buf = (t & 1) * 8192;
        if (kt == 0) {
            __syncthreads();
            int n = n0 + nv;
            const char* qp = (const char*)(g_qh + ((size_t)(bm * NVIEW + n) * QLEN + q0) * DH);
#pragma unroll
            for (int it = 0; it < 8; it++) {
                int i = tid + it * 128;
                int rr = i >> 3, c = i & 7;
                cp16(qs_base + rr * 128 + ((c ^ (rr & 7)) << 4), qp + i * 16);
            }
            cp_commit();
        }

        cp_wait<0>();
        __syncthreads();

        if (kt == 0) {
            int n = n0 + nv;
#pragma unroll
            for (int rg = 0; rg < 2; rg++) {
#pragma unroll
                for (int ks = 0; ks < 4; ks++) {
                    int row = 32 * w + 16 * rg + (lane & 7) + (((lane >> 3) & 1) << 3);
                    int ch = 2 * ks + (lane >> 4);
                    ldsm_x4(qa[rg][ks], qs_base + row * 128 + ((ch ^ (row & 7)) << 4));
                }
                bias[rg][0] = g_maskb[n * QLEN + q0 + 32 * w + 16 * rg + (lane >> 2)] * LOG2E;
                bias[rg][1] = g_maskb[n * QLEN + q0 + 32 * w + 16 * rg + (lane >> 2) + 8] * LOG2E;
            }
        }

        if (t < 29) {
            int tn = t + 1;
            int nn = n0 + tn / 10, nkt = tn % 10;
            int nbuf = (tn & 1) * 8192;
            const char* kp = kroot + ((size_t)(nn * KLEN + nkt * 64) * DH) * 2;
            const char* vp = vroot + ((size_t)(nn * KLEN + nkt * 64) * DH) * 2;
#pragma unroll
            for (int it = 0; it < 4; it++) {
                int i = tid + it * 128;
                int rr = i >> 3, c = i & 7;
                int sw = rr * 128 + ((c ^ (rr & 7)) << 4);
                cp16(ks_base + nbuf + sw, kp + i * 16);
                cp16(vs_base + nbuf + sw, vp + i * 16);
            }
            cp_commit();
        }

        float s[2][8][4];
#pragma unroll
        for (int rg = 0; rg < 2; rg++)
#pragma unroll
            for (int nb = 0; nb < 8; nb++)
#pragma unroll
                for (int i = 0; i < 4; i++) s[rg][nb][i] = 0.f;
#pragma unroll
        for (int ks = 0; ks < 4; ks++) {
#pragma unroll
            for (int tt = 0; tt < 4; tt++) {
                uint32_t bf[4];
                int key = 16 * tt + (lane & 7) + ((lane >> 4) << 3);
                int ch = 2 * ks + ((lane >> 3) & 1);
                ldsm_x4(bf, ks_base + buf + key * 128 + ((ch ^ (key & 7)) << 4));
                mma_bf16(s[0][2 * tt], qa[0][ks], bf[0], bf[1]);
                mma_bf16(s[0][2 * tt + 1], qa[0][ks], bf[2], bf[3]);
                mma_bf16(s[1][2 * tt], qa[1][ks], bf[0], bf[1]);
                mma_bf16(s[1][2 * tt + 1], qa[1][ks], bf[2], bf[3]);
            }
        }

#pragma unroll
        for (int rg = 0; rg < 2; rg++) {
            float sum0 = 0.f, sum1 = 0.f;
#pragma unroll
            for (int nb = 0; nb < 8; nb++) {
                s[rg][nb][0] = ex2(fmaf(s[rg][nb][0], SCALE2, bias[rg][0]));
                s[rg][nb][1] = ex2(fmaf(s[rg][nb][1], SCALE2, bias[rg][0]));
                s[rg][nb][2] = ex2(fmaf(s[rg][nb][2], SCALE2, bias[rg][1]));
                s[rg][nb][3] = ex2(fmaf(s[rg][nb][3], SCALE2, bias[rg][1]));
                sum0 += s[rg][nb][0] + s[rg][nb][1];
                sum1 += s[rg][nb][2] + s[rg][nb][3];
            }
            row_l[rg][0] += sum0;
            row_l[rg][1] += sum1;
        }

#pragma unroll
        for (int ks = 0; ks < 4; ks++) {
            uint32_t pa[2][4];
#pragma unroll
            for (int rg = 0; rg < 2; rg++) {
                pa[rg][0] = packbf(s[rg][2 * ks][0], s[rg][2 * ks][1]);
                pa[rg][1] = packbf(s[rg][2 * ks][2], s[rg][2 * ks][3]);
                pa[rg][2] = packbf(s[rg][2 * ks + 1][0], s[rg][2 * ks + 1][1]);
                pa[rg][3] = packbf(s[rg][2 * ks + 1][2], s[rg][2 * ks + 1][3]);
            }
#pragma unroll
            for (int tt = 0; tt < 4; tt++) {
                uint32_t bf[4];
                int key = 16 * ks + (lane & 7) + (((lane >> 3) & 1) << 3);
                int ch = 2 * tt + (lane >> 4);
                ldsm_x4_t(bf, vs_base + buf + key * 128 + ((ch ^ (key & 7)) << 4));
                mma_bf16(o[0][2 * tt], pa[0], bf[0], bf[1]);
                mma_bf16(o[0][2 * tt + 1], pa[0], bf[2], bf[3]);
                mma_bf16(o[1][2 * tt], pa[1], bf[0], bf[1]);
                mma_bf16(o[1][2 * tt + 1], pa[1], bf[2], bf[3]);
            }
        }
    }

#pragma unroll
    for (int rg = 0; rg < 2; rg++) {
        float l0 = row_l[rg][0], l1 = row_l[rg][1];
        l0 += __shfl_xor_sync(0xffffffffu, l0, 1);
        l0 += __shfl_xor_sync(0xffffffffu, l0, 2);
        l1 += __shfl_xor_sync(0xffffffffu, l1, 1);
        l1 += __shfl_xor_sync(0xffffffffu, l1, 2);

        int row0 = q0 + 32 * w + 16 * rg + (lane >> 2);
        __nv_bfloat16* po = g_po[split] + ((size_t)b * QLEN) * MD;
#pragma unroll
        for (int nb = 0; nb < 8; nb++) {
            int dh = 8 * nb + 2 * (lane & 3);
            *(uint32_t*)&po[(size_t)row0 * MD + m * DH + dh] =
                packbf(o[rg][nb][0], o[rg][nb][1]);
            *(uint32_t*)&po[(size_t)(row0 + 8) * MD + m * DH + dh] =
                packbf(o[rg][nb][2], o[rg][nb][3]);
        }
        if ((lane & 3) == 0) {
            g_pl[split][bm * QLEN + row0] = l0;
            g_pl[split][bm * QLEN + row0 + 8] = l1;
        }
    }
}

// ---------------- epilogue: 16-row tiles, grid (64,4), tensor-core ------------
__device__ __forceinline__ void ln_stats128(const float* row, int lane,
                                            float& mean, float& rstd) {
    float s = 0.f;
#pragma unroll
    for (int kk = 0; kk < 4; kk++) s += row[lane + 32 * kk];
#pragma unroll
    for (int o = 16; o; o >>= 1) s += __shfl_xor_sync(0xffffffffu, s, o);
    mean = s * (1.0f / 128.0f);
    float vv = 0.f;
#pragma unroll
    for (int kk = 0; kk < 4; kk++) { float t = row[lane + 32 * kk] - mean; vv += t * t; }
#pragma unroll
    for (int o = 16; o; o >>= 1) vv += __shfl_xor_sync(0xffffffffu, vv, o);
    rstd = rsqrtf(vv * (1.0f / 128.0f) + 1e-5f);
}

// smem: Zs 8KB | P0 4KB | P1 4KB | Zb 4KB | Wb0 32KB | Wb1 32KB = 84KB
#define EPI_SMEM (8192 + 4096*3 + 32768*2)
__global__ __launch_bounds__(128, 2) void epilogue_kernel(
        const float* __restrict__ skip, const float* __restrict__ bp,
        const float* __restrict__ preg, const float* __restrict__ preb,
        const float* __restrict__ b1, const float* __restrict__ b2,
        const float* __restrict__ postg, const float* __restrict__ postb,
        float* __restrict__ out) {
    extern __shared__ char esm[];
    float* Zs = (float*)esm;                 // [16][128]
    char* P0 = esm + 8192;
    char* P1 = esm + 12288;
    char* Zb = esm + 16384;
    uint32_t p0_base = smem_u32(P0), p1_base = smem_u32(P1), zb_base = smem_u32(Zb);
    uint32_t wb0 = smem_u32(esm + 20480), wb1 = smem_u32(esm + 53248);

    int tid = threadIdx.x, lane = tid & 31, w = tid >> 5;
    int b = blockIdx.y, q0 = blockIdx.x * 16;
    int colh = 32 * w, cb0 = colh >> 3;      // warp covers 32 output cols
    int rA = (lane >> 2), rB = rA + 8;

    // G0: Wp panel 0
    for (int i = tid; i < 2048; i += 128) cp16(wb0 + i * 16, g_wep + i * 16);
    cp_commit();

    // recombine (bf16 partials): A panels P0 (cols 0..127) / P1 (128..255)
    for (int i = tid; i < 16 * 64; i += 128) {
        int row = i >> 6, c4 = i & 63;
        int q = q0 + row, m = c4 >> 4;
        float l = g_pl[0][(b * 4 + m) * QLEN + q] + g_pl[1][(b * 4 + m) * QLEN + q];
        float inv = 1.0f / l;
        size_t off = ((size_t)(b * QLEN + q)) * MD + c4 * 4;
        uint2 a0 = *(const uint2*)&g_po[0][off];
        uint2 a1 = *(const uint2*)&g_po[1][off];
        float2 f00 = bf2f(a0.x), f01 = bf2f(a0.y);
        float2 f10 = bf2f(a1.x), f11 = bf2f(a1.y);
        char* pan = (c4 < 32) ? P0 : P1;
        int pl = (c4 * 2) & 63;
        uint32_t v0 = packbf((f00.x + f10.x) * inv, (f00.y + f10.y) * inv);
        uint32_t v1 = packbf((f01.x + f11.x) * inv, (f01.y + f11.y) * inv);
        *(uint32_t*)(pan + row * 256 + (((pl >> 2) ^ (row & 7)) << 4) + ((pl & 3) << 2)) = v0;
        int pl1 = pl + 1;
        *(uint32_t*)(pan + row * 256 + (((pl1 >> 2) ^ (row & 7)) << 4) + ((pl1 & 3) << 2)) = v1;
    }

    // G1: Wp panel 1
    for (int i = tid; i < 2048; i += 128) cp16(wb1 + i * 16, g_wep + 32768 + i * 16);
    cp_commit();
    __syncthreads();                         // P0,P1 ready

    // ---- GEMM1: Z = A @ Wp (K=256) ----
    float acc[4][4];
#pragma unroll
    for (int nb = 0; nb < 4; nb++)
#pragma unroll
        for (int i = 0; i < 4; i++) acc[nb][i] = 0.f;

    cp_wait<1>(); __syncthreads();           // Wb0 (Wp0)
    epi_gemm16(acc, p0_base, wb0, lane, cb0);
    __syncthreads();
    for (int i = tid; i < 2048; i += 128) cp16(wb0 + i * 16, g_wep + 2 * 32768 + i * 16);  // W1 n0
    cp_commit();
    cp_wait<1>(); __syncthreads();           // Wb1 (Wp1)
    epi_gemm16(acc, p1_base, wb1, lane, cb0);

#pragma unroll
    for (int nb = 0; nb < 4; nb++) {
        int c = colh + 8 * nb + 2 * (lane & 3);
        Zs[rA * 128 + c]     = acc[nb][0] + bp[c]     + skip[((size_t)b * 128 + c) * 1024 + q0 + rA];
        Zs[rA * 128 + c + 1] = acc[nb][1] + bp[c + 1] + skip[((size_t)b * 128 + c + 1) * 1024 + q0 + rA];
        Zs[rB * 128 + c]     = acc[nb][2] + bp[c]     + skip[((size_t)b * 128 + c) * 1024 + q0 + rB];
        Zs[rB * 128 + c + 1] = acc[nb][3] + bp[c + 1] + skip[((size_t)b * 128 + c + 1) * 1024 + q0 + rB];
    }
    __syncthreads();
    for (int i = tid; i < 2048; i += 128) cp16(wb1 + i * 16, g_wep + 3 * 32768 + i * 16);  // W1 n1
    cp_commit();

    // pre-LN: warp w handles rows 4w..4w+3; fp32 back + bf16 panel Zb
#pragma unroll
    for (int rr = 0; rr < 4; rr++) {
        int r = w * 4 + rr;
        float mean, rstd;
        ln_stats128(&Zs[r * 128], lane, mean, rstd);
        int d0 = 2 * lane, d1 = 64 + 2 * lane;
        float z0 = (Zs[r * 128 + d0] - mean) * rstd * preg[d0] + preb[d0];
        float z1 = (Zs[r * 128 + d0 + 1] - mean) * rstd * preg[d0 + 1] + preb[d0 + 1];
        float z2 = (Zs[r * 128 + d1] - mean) * rstd * preg[d1] + preb[d1];
        float z3 = (Zs[r * 128 + d1 + 1] - mean) * rstd * preg[d1 + 1] + preb[d1 + 1];
        __syncwarp();
        Zs[r * 128 + d0] = z0; Zs[r * 128 + d0 + 1] = z1;
        Zs[r * 128 + d1] = z2; Zs[r * 128 + d1 + 1] = z3;
        int p = lane, p2 = lane + 32;
        *(uint32_t*)(Zb + r * 256 + (((p >> 2) ^ (r & 7)) << 4) + ((p & 3) << 2)) = packbf(z0, z1);
        *(uint32_t*)(Zb + r * 256 + (((p2 >> 2) ^ (r & 7)) << 4) + ((p2 & 3) << 2)) = packbf(z2, z3);
    }
    __syncthreads();

    // ---- GEMM2: H = gelu(Z @ W1 + b1) -> P0 / P1 ----
    cp_wait<1>(); __syncthreads();           // Wb0 (W1 n0)
    {
        float a2[4][4];
#pragma unroll
        for (int nb = 0; nb < 4; nb++)
#pragma unroll
            for (int i = 0; i < 4; i++) a2[nb][i] = 0.f;
        epi_gemm16(a2, zb_base, wb0, lane, cb0);
#pragma unroll
        for (int nb = 0; nb < 4; nb++) {
            int cl = colh + 8 * nb + 2 * (lane & 3);
            float x0 = a2[nb][0] + b1[cl],     x1 = a2[nb][1] + b1[cl + 1];
            float x2 = a2[nb][2] + b1[cl],     x3 = a2[nb][3] + b1[cl + 1];
            x0 = 0.5f * x0 * (1.0f + erff(x0 * 0.70710678118f));
            x1 = 0.5f * x1 * (1.0f + erff(x1 * 0.70710678118f));
            x2 = 0.5f * x2 * (1.0f + erff(x2 * 0.70710678118f));
            x3 = 0.5f * x3 * (1.0f + erff(x3 * 0.70710678118f));
            int pl = cl >> 1;
            *(uint32_t*)(P0 + rA * 256 + (((pl >> 2) ^ (rA & 7)) << 4) + ((pl & 3) << 2)) = packbf(x0, x1);
            *(uint32_t*)(P0 + rB * 256 + (((pl >> 2) ^ (rB & 7)) << 4) + ((pl & 3) << 2)) = packbf(x2, x3);
        }
    }
    __syncthreads();
    for (int i = tid; i < 2048; i += 128) cp16(wb0 + i * 16, g_wep + 4 * 32768 + i * 16);  // W2 k0
    cp_commit();
    cp_wait<1>(); __syncthreads();           // Wb1 (W1 n1)
    {
        float a2[4][4];
#pragma unroll
        for (int nb = 0; nb < 4; nb++)
#pragma unroll
            for (int i = 0; i < 4; i++) a2[nb][i] = 0.f;
        epi_gemm16(a2, zb_base, wb1, lane, cb0);
#pragma unroll
        for (int nb = 0; nb < 4; nb++) {
            int cl = colh + 8 * nb + 2 * (lane & 3);
            float x0 = a2[nb][0] + b1[128 + cl],     x1 = a2[nb][1] + b1[128 + cl + 1];
            float x2 = a2[nb][2] + b1[128 + cl],     x3 = a2[nb][3] + b1[128 + cl + 1];
            x0 = 0.5f * x0 * (1.0f + erff(x0 * 0.70710678118f));
            x1 = 0.5f * x1 * (1.0f + erff(x1 * 0.70710678118f));
            x2 = 0.5f * x2 * (1.0f + erff(x2 * 0.70710678118f));
            x3 = 0.5f * x3 * (1.0f + erff(x3 * 0.70710678118f));
            int pl = cl >> 1;
            *(uint32_t*)(P1 + rA * 256 + (((pl >> 2) ^ (rA & 7)) << 4) + ((pl & 3) << 2)) = packbf(x0, x1);
            *(uint32_t*)(P1 + rB * 256 + (((pl >> 2) ^ (rB & 7)) << 4) + ((pl & 3) << 2)) = packbf(x2, x3);
        }
    }
    __syncthreads();
    for (int i = tid; i < 2048; i += 128) cp16(wb1 + i * 16, g_wep + 5 * 32768 + i * 16);  // W2 k1
    cp_commit();

    // ---- GEMM3: U = H @ W2 (K=256) + b2 + Z ----
    float a3[4][4];
#pragma unroll
    for (int nb = 0; nb < 4; nb++)
#pragma unroll
        for (int i = 0; i < 4; i++) a3[nb][i] = 0.f;
    cp_wait<1>(); __syncthreads();           // Wb0 (W2 k0)
    epi_gemm16(a3, p0_base, wb0, lane, cb0);
    cp_wait<0>(); __syncthreads();           // Wb1 (W2 k1)
    epi_gemm16(a3, p1_base, wb1, lane, cb0);

#pragma unroll
    for (int nb = 0; nb < 4; nb++) {
        int c = colh + 8 * nb + 2 * (lane & 3);
        Zs[rA * 128 + c]     = a3[nb][0] + b2[c]     + Zs[rA * 128 + c];
        Zs[rA * 128 + c + 1] = a3[nb][1] + b2[c + 1] + Zs[rA * 128 + c + 1];
        Zs[rB * 128 + c]     = a3[nb][2] + b2[c]     + Zs[rB * 128 + c];
        Zs[rB * 128 + c + 1] = a3[nb][3] + b2[c + 1] + Zs[rB * 128 + c + 1];
    }
    __syncthreads();

    // post-LN + transposed store
#pragma unroll
    for (int rr = 0; rr < 4; rr++) {
        int r = w * 4 + rr;
        float mean, rstd;
        ln_stats128(&Zs[r * 128], lane, mean, rstd);
        int q = q0 + r;
#pragma unroll
        for (int kk = 0; kk < 4; kk++) {
            int d = lane + 32 * kk;
            float val = (Zs[r * 128 + d] - mean) * rstd * postg[d] + postb[d];
            out[((size_t)b * 128 + d) * 1024 + q] = val;
        }
    }
}

// ---------------- launch -------------------------------------------------------
extern "C" void kernel_launch(void* const* d_in, const int* in_sizes, int n_in,
                              void* d_out, int out_size) {
    const float* q    = (const float*)d_in[0];
    const float* k    = (const float*)d_in[1];
    const float* v    = (const float*)d_in[2];
    const float* skip = (const float*)d_in[3];
    const unsigned char* mask = (const unsigned char*)d_in[4];
    const float* lnq_g = (const float*)d_in[5];
    const float* lnq_b = (const float*)d_in[6];
    const float* lnk_g = (const float*)d_in[7];
    const float* lnk_b = (const float*)d_in[8];
    const float* lnv_g = (const float*)d_in[9];
    const float* lnv_b = (const float*)d_in[10];
    const float* Wq = (const float*)d_in[11];
    const float* bq = (const float*)d_in[12];
    const float* Wk = (const float*)d_in[13];
    const float* bk = (const float*)d_in[14];
    const float* Wv = (const float*)d_in[15];
    const float* bv = (const float*)d_in[16];
    const float* Wp = (const float*)d_in[17];
    const float* bp = (const float*)d_in[18];
    const float* pre_g = (const float*)d_in[19];
    const float* pre_b = (const float*)d_in[20];
    const float* W1 = (const float*)d_in[21];
    const float* b1 = (const float*)d_in[22];
    const float* W2 = (const float*)d_in[23];
    const float* b2 = (const float*)d_in[24];
    const float* post_g = (const float*)d_in[25];
    const float* post_b = (const float*)d_in[26];
    float* out = (float*)d_out;

    cudaFuncSetAttribute(ln_proj_tc_kernel, cudaFuncAttributeMaxDynamicSharedMemorySize, LNPROJ_SMEM);
    cudaFuncSetAttribute(attn_kernel, cudaFuncAttributeMaxDynamicSharedMemorySize, ATT_SMEM);
    cudaFuncSetAttribute(epilogue_kernel, cudaFuncAttributeMaxDynamicSharedMemorySize, EPI_SMEM);

    prep_kernel<<<385, 256>>>(Wq, Wk, Wv, Wp, W1, W2, mask);
    ln_proj_tc_kernel<<<dim3(36, NVIEW, BATCH), 256, LNPROJ_SMEM>>>(
        q, k, v, lnq_g, lnq_b, lnk_g, lnk_b, lnv_g, lnv_b, bq, bk, bv);
    attn_kernel<<<dim3(8, 16, 2), 128, ATT_SMEM>>>();
    epilogue_kernel<<<dim3(64, BATCH), 128, EPI_SMEM>>>(skip, bp, pre_g, pre_b,
                                                        b1, b2, post_g, post_b, out);
}